// round 8
// baseline (speedup 1.0000x reference)
#include <cuda_runtime.h>
#include <math.h>
#include <stdint.h>

#define MDL   4
#define CDIM  1000
#define NV4   250                       // CDIM/4 float4 per row
#define WPB   7                         // warps per block (one sample-stream each)
#define NTHR  (WPB * 32)                // 224
#define LOGC  6.90775527898213705f     // log(1000)
#define ROWB  (CDIM * 4)                // 4000 B per model row (16B-divisible)
#define SLOTB (MDL * ROWB)              // 16000 B: one sample (4 rows)
#define DEPTH 2                         // per-warp ring depth
#define QW    8                         // samples per warp
#define QB    (WPB * QW)                // 56 samples per block
#define DYNSM (WPB * DEPTH * SLOTB)     // 224000 B dynamic smem

// Device globals (no allocation). Zero-init at load; last block restores zeros
// every launch -> deterministic graph replays.
__device__ double   g_acc[2];
__device__ unsigned g_count;

__device__ __forceinline__ uint32_t smem_u32(const void* p) {
    uint32_t a;
    asm("{ .reg .u64 t; cvta.to.shared.u64 t, %1; cvt.u32.u64 %0, t; }"
        : "=r"(a) : "l"(p));
    return a;
}
__device__ __forceinline__ void mbar_init(uint32_t mbar, uint32_t cnt) {
    asm volatile("mbarrier.init.shared.b64 [%0], %1;" :: "r"(mbar), "r"(cnt) : "memory");
}
__device__ __forceinline__ void mbar_expect_tx(uint32_t mbar, uint32_t bytes) {
    asm volatile("mbarrier.arrive.expect_tx.shared.b64 _, [%0], %1;"
                 :: "r"(mbar), "r"(bytes) : "memory");
}
__device__ __forceinline__ void mbar_wait(uint32_t mbar, uint32_t parity) {
    uint32_t done;
    asm volatile(
        "{\n\t.reg .pred p;\n\t"
        "mbarrier.try_wait.parity.acquire.cta.shared::cta.b64 p, [%1], %2;\n\t"
        "selp.b32 %0, 1, 0, p;\n\t}"
        : "=r"(done) : "r"(mbar), "r"(parity) : "memory");
    if (!done) {
        asm volatile(
            "{\n\t.reg .pred P1;\n\t"
            "WL_%=:\n\t"
            "mbarrier.try_wait.parity.acquire.cta.shared::cta.b64 P1, [%0], %1, 0x989680;\n\t"
            "@P1 bra.uni WD_%=;\n\t"
            "bra.uni WL_%=;\n\t"
            "WD_%=:\n\t}"
            :: "r"(mbar), "r"(parity) : "memory");
    }
}
__device__ __forceinline__ void bulk_g2s(uint32_t dst, const void* src,
                                         uint32_t bytes, uint32_t mbar) {
    asm volatile(
        "cp.async.bulk.shared::cluster.global.mbarrier::complete_tx::bytes "
        "[%0], [%1], %2, [%3];"
        :: "r"(dst), "l"(src), "r"(bytes), "r"(mbar) : "memory");
}

extern __shared__ char stage_mem[];     // WPB * DEPTH * SLOTB

__global__ __launch_bounds__(NTHR) void cmcl_warp(
    const float* __restrict__ logits,   // (M, B, C) fp32
    const int*   __restrict__ t32,      // targets viewed as int32 words
    float* __restrict__ loss_out,       // scalar or null
    float* __restrict__ oracle,         // (B, C) or null
    float* __restrict__ idx_out,        // (B,)  or null
    int B)
{
    __shared__ alignas(8) unsigned long long s_mbar[WPB][DEPTH];
    __shared__ int s_is64;

    const int tid  = threadIdx.x;
    const int w    = tid >> 5;          // warp = sample stream
    const int lane = tid & 31;

    if (tid == 0) {
        // int64 vs int32 targets: true int64 (<1000, LE) has zero odd words;
        // 16 random int32 words matching that: p ~ 1e-48.
        int is64 = 1;
        #pragma unroll
        for (int k = 0; k < 16; k++)
            if (t32[2 * k + 1] != 0) { is64 = 0; break; }
        s_is64 = is64;
    }
    if (lane == 0) {
        mbar_init(smem_u32(&s_mbar[w][0]), 1);
        mbar_init(smem_u32(&s_mbar[w][1]), 1);
    }
    __syncthreads();
    const int is64 = s_is64;

    // This warp's contiguous sample range.
    const int wbase = blockIdx.x * QB + w * QW;
    int cnt = B - wbase;
    if (cnt > QW) cnt = QW;
    if (cnt < 0)  cnt = 0;

    char* ring = stage_mem + w * (DEPTH * SLOTB);
    const uint32_t ring0 = smem_u32(ring);

    double acc0 = 0.0, acc1 = 0.0;      // lane 0's stream-partial sums

    // Fill slot `s` with sample wbase+n (4 model rows).
    auto fill = [&](int s, int n) {
        uint32_t mb = smem_u32(&s_mbar[w][s]);
        mbar_expect_tx(mb, SLOTB);
        #pragma unroll
        for (int m = 0; m < MDL; m++)
            bulk_g2s(ring0 + s * SLOTB + m * ROWB,
                     logits + ((size_t)m * B + wbase + n) * CDIM,
                     ROWB, mb);
    };

    if (lane == 0) {
        if (cnt > 0) fill(0, 0);
        if (cnt > 1) fill(1, 1);
    }

    for (int n = 0; n < cnt; n++) {
        const int s  = n & 1;
        const int ph = (n >> 1) & 1;
        mbar_wait(smem_u32(&s_mbar[w][s]), ph);

        const int b = wbase + n;
        const char* slot = ring + s * SLOTB;

        // Accumulate all 4 model rows of this sample.
        // Winner score (ce-ent) = mean(x) - x_t + logC: logsumexp cancels
        // analytically, so the argmin (and the oracle rows it picks) is
        // exp-free and exact in fp32. __expf/__logf error only touches the
        // scalar loss (abs tol ~2.7e-2).
        float ssum[MDL] = {0.f, 0.f, 0.f, 0.f};
        float sexp[MDL] = {0.f, 0.f, 0.f, 0.f};
        #pragma unroll
        for (int m = 0; m < MDL; m++) {
            const float4* __restrict__ row = (const float4*)(slot + m * ROWB);
            #pragma unroll
            for (int k = 0; k < 8; k++) {
                int i = lane + 32 * k;
                if (i < NV4) {
                    float4 v = row[i];
                    ssum[m] += (v.x + v.y) + (v.z + v.w);
                    sexp[m] += (__expf(v.x) + __expf(v.y))
                             + (__expf(v.z) + __expf(v.w));
                }
            }
        }
        // Interleaved shfl trees (8 independent chains hide SHFL latency).
        #pragma unroll
        for (int off = 16; off > 0; off >>= 1) {
            #pragma unroll
            for (int m = 0; m < MDL; m++) {
                ssum[m] += __shfl_xor_sync(0xFFFFFFFFu, ssum[m], off);
                sexp[m] += __shfl_xor_sync(0xFFFFFFFFu, sexp[m], off);
            }
        }

        int win = 0;
        if (lane == 0) {
            int tgt = is64 ? t32[2 * b] : t32[b];
            float best = 0.0f, entsum = 0.0f;
            #pragma unroll
            for (int m = 0; m < MDL; m++) {
                float tval = *(const float*)(slot + m * ROWB + 4 * tgt);
                float mean = ssum[m] * (1.0f / CDIM);
                float sc   = mean - tval;            // ce - ent - logC
                entsum += __logf(sexp[m]) - mean - LOGC;
                if (m == 0 || sc < best) {           // strict <: jax first-min
                    if (m == 0) { best = sc; }
                    else        { best = sc; win = m; }
                }
            }
            acc0 += (double)(best + LOGC);           // ce_win - ent_win
            acc1 += (double)entsum;
            if (idx_out) idx_out[b] = (float)win;
        }
        win = __shfl_sync(0xFFFFFFFFu, win, 0);

        // Oracle row copy straight from smem (vector loads, scalar stores:
        // dst may be only 4B-aligned).
        if (oracle) {
            const float4* __restrict__ src4 =
                (const float4*)(slot + win * ROWB);
            float* __restrict__ dst = oracle + (size_t)b * CDIM;
            #pragma unroll
            for (int k = 0; k < 8; k++) {
                int i = lane + 32 * k;
                if (i < NV4) {
                    float4 v = src4[i];
                    dst[4 * i + 0] = v.x;
                    dst[4 * i + 1] = v.y;
                    dst[4 * i + 2] = v.z;
                    dst[4 * i + 3] = v.w;
                }
            }
        }

        __syncwarp();                   // all lanes done reading slot s
        if (lane == 0 && n + DEPTH < cnt) fill(s, n + DEPTH);
    }

    // Stream tail: one atomic pair per warp; block counter finalizes.
    if (lane == 0 && cnt > 0) {
        atomicAdd(&g_acc[0], acc0);
        atomicAdd(&g_acc[1], acc1);
        __threadfence();
    }
    __syncthreads();
    if (tid == 0) {
        unsigned t = atomicAdd(&g_count, 1u);
        if (t == (unsigned)gridDim.x - 1u) {
            double a0 = __longlong_as_double(
                atomicExch((unsigned long long*)&g_acc[0], 0ull));
            double a1 = __longlong_as_double(
                atomicExch((unsigned long long*)&g_acc[1], 0ull));
            if (loss_out) loss_out[0] = (float)((a0 + a1) / (double)B);
            g_count = 0u;
            __threadfence();
        }
    }
}

extern "C" void kernel_launch(void* const* d_in, const int* in_sizes, int n_in,
                              void* d_out, int out_size)
{
    const float* logits = (const float*)d_in[0];
    const int*   t32    = (const int*)d_in[1];
    const int B = in_sizes[1];                 // 8192

    float* out = (float*)d_out;
    const long long bc = (long long)B * CDIM;

    // Output layout: tuple (new_loss, oracle_logits, min_index) flattened.
    float* loss_p   = nullptr;
    float* oracle_p = nullptr;
    float* idx_p    = nullptr;
    long long osz = (long long)out_size;
    if (osz >= 1 + bc + B) {                   // full tuple
        loss_p   = out;
        oracle_p = out + 1;
        idx_p    = out + 1 + bc;
    } else if (osz == bc + B) {                // (oracle, idx)
        oracle_p = out;
        idx_p    = out + bc;
    } else if (osz == bc) {                    // oracle only
        oracle_p = out;
    } else if (osz == B) {                     // idx only
        idx_p = out;
    } else {                                   // scalar loss only
        loss_p = out;
    }

    const int grid = (B + QB - 1) / QB;        // 147 blocks (~1 per SM)

    cudaFuncSetAttribute(cmcl_warp,
                         cudaFuncAttributeMaxDynamicSharedMemorySize, DYNSM);
    cmcl_warp<<<grid, NTHR, DYNSM>>>(logits, t32, loss_p, oracle_p, idx_p, B);
}

// round 9
// speedup vs baseline: 1.0453x; 1.0453x over previous
#include <cuda_runtime.h>
#include <math.h>
#include <stdint.h>

#define MDL   4
#define CDIM  1000
#define NV4   250                       // CDIM/4 float4 per row
#define WPB   7                         // warps per block (one sample-stream each)
#define NTHR  (WPB * 32)                // 224
#define LOGC  6.90775527898213705f     // log(1000)
#define ROWB  (CDIM * 4)                // 4000 B per model row (16B-divisible)
#define SLOTB (MDL * ROWB)              // 16000 B: one sample (4 rows)
#define DEPTH 2                         // per-warp ring depth
#define QW    8                         // samples per warp
#define QB    (WPB * QW)                // 56 samples per block
#define DYNSM (WPB * DEPTH * SLOTB)     // 224000 B dynamic smem

// Device globals (no allocation). Zero-init at load; last block restores zeros
// every launch -> deterministic graph replays.
__device__ double   g_acc[2];
__device__ unsigned g_count;

__device__ __forceinline__ uint32_t smem_u32(const void* p) {
    uint32_t a;
    asm("{ .reg .u64 t; cvta.to.shared.u64 t, %1; cvt.u32.u64 %0, t; }"
        : "=r"(a) : "l"(p));
    return a;
}
__device__ __forceinline__ void mbar_init(uint32_t mbar, uint32_t cnt) {
    asm volatile("mbarrier.init.shared.b64 [%0], %1;" :: "r"(mbar), "r"(cnt) : "memory");
}
__device__ __forceinline__ void mbar_expect_tx(uint32_t mbar, uint32_t bytes) {
    asm volatile("mbarrier.arrive.expect_tx.shared.b64 _, [%0], %1;"
                 :: "r"(mbar), "r"(bytes) : "memory");
}
__device__ __forceinline__ void mbar_wait(uint32_t mbar, uint32_t parity) {
    uint32_t done;
    asm volatile(
        "{\n\t.reg .pred p;\n\t"
        "mbarrier.try_wait.parity.acquire.cta.shared::cta.b64 p, [%1], %2;\n\t"
        "selp.b32 %0, 1, 0, p;\n\t}"
        : "=r"(done) : "r"(mbar), "r"(parity) : "memory");
    if (!done) {
        asm volatile(
            "{\n\t.reg .pred P1;\n\t"
            "WL_%=:\n\t"
            "mbarrier.try_wait.parity.acquire.cta.shared::cta.b64 P1, [%0], %1, 0x989680;\n\t"
            "@P1 bra.uni WD_%=;\n\t"
            "bra.uni WL_%=;\n\t"
            "WD_%=:\n\t}"
            :: "r"(mbar), "r"(parity) : "memory");
    }
}
__device__ __forceinline__ void bulk_g2s(uint32_t dst, const void* src,
                                         uint32_t bytes, uint32_t mbar) {
    asm volatile(
        "cp.async.bulk.shared::cluster.global.mbarrier::complete_tx::bytes "
        "[%0], [%1], %2, [%3];"
        :: "r"(dst), "l"(src), "r"(bytes), "r"(mbar) : "memory");
}

extern __shared__ char stage_mem[];     // WPB * DEPTH * SLOTB

__global__ __launch_bounds__(NTHR) void cmcl_warp(
    const float* __restrict__ logits,   // (M, B, C) fp32
    const int*   __restrict__ t32,      // targets viewed as int32 words
    float* __restrict__ loss_out,       // scalar or null
    float* __restrict__ oracle,         // (B, C) or null
    float* __restrict__ idx_out,        // (B,)  or null
    int B)
{
    __shared__ alignas(8) unsigned long long s_mbar[WPB][DEPTH];
    __shared__ int s_is64;

    const int tid  = threadIdx.x;
    const int w    = tid >> 5;          // warp = sample stream
    const int lane = tid & 31;

    if (tid == 0) {
        // int64 vs int32 targets: true int64 (<1000, LE) has zero odd words;
        // 16 random int32 words matching that: p ~ 1e-48.
        int is64 = 1;
        #pragma unroll
        for (int k = 0; k < 16; k++)
            if (t32[2 * k + 1] != 0) { is64 = 0; break; }
        s_is64 = is64;
    }
    if (lane == 0) {
        mbar_init(smem_u32(&s_mbar[w][0]), 1);
        mbar_init(smem_u32(&s_mbar[w][1]), 1);
    }
    __syncthreads();
    const int is64 = s_is64;

    // This warp's contiguous sample range.
    const int wbase = blockIdx.x * QB + w * QW;
    int cnt = B - wbase;
    if (cnt > QW) cnt = QW;
    if (cnt < 0)  cnt = 0;

    char* ring = stage_mem + w * (DEPTH * SLOTB);
    const uint32_t ring0 = smem_u32(ring);

    double acc0 = 0.0, acc1 = 0.0;      // lane 0's stream-partial sums

    // Fill slot `s` with sample wbase+n (4 model rows).
    auto fill = [&](int s, int n) {
        uint32_t mb = smem_u32(&s_mbar[w][s]);
        mbar_expect_tx(mb, SLOTB);
        #pragma unroll
        for (int m = 0; m < MDL; m++)
            bulk_g2s(ring0 + s * SLOTB + m * ROWB,
                     logits + ((size_t)m * B + wbase + n) * CDIM,
                     ROWB, mb);
    };

    if (lane == 0) {
        if (cnt > 0) fill(0, 0);
        if (cnt > 1) fill(1, 1);
    }

    for (int n = 0; n < cnt; n++) {
        const int s  = n & 1;
        const int ph = (n >> 1) & 1;
        mbar_wait(smem_u32(&s_mbar[w][s]), ph);

        const int b = wbase + n;
        const char* slot = ring + s * SLOTB;

        // Accumulate all 4 model rows of this sample.
        // Winner score (ce-ent) = mean(x) - x_t + logC: logsumexp cancels
        // analytically, so the argmin (and the oracle rows it picks) is
        // exp-free and exact in fp32. __expf/__logf error only touches the
        // scalar loss (abs tol ~2.7e-2).
        float ssum[MDL] = {0.f, 0.f, 0.f, 0.f};
        float sexp[MDL] = {0.f, 0.f, 0.f, 0.f};
        #pragma unroll
        for (int m = 0; m < MDL; m++) {
            const float4* __restrict__ row = (const float4*)(slot + m * ROWB);
            #pragma unroll
            for (int k = 0; k < 8; k++) {
                int i = lane + 32 * k;
                if (i < NV4) {
                    float4 v = row[i];
                    ssum[m] += (v.x + v.y) + (v.z + v.w);
                    sexp[m] += (__expf(v.x) + __expf(v.y))
                             + (__expf(v.z) + __expf(v.w));
                }
            }
        }
        // Interleaved shfl trees (8 independent chains hide SHFL latency).
        #pragma unroll
        for (int off = 16; off > 0; off >>= 1) {
            #pragma unroll
            for (int m = 0; m < MDL; m++) {
                ssum[m] += __shfl_xor_sync(0xFFFFFFFFu, ssum[m], off);
                sexp[m] += __shfl_xor_sync(0xFFFFFFFFu, sexp[m], off);
            }
        }

        int win = 0;
        if (lane == 0) {
            int tgt = is64 ? t32[2 * b] : t32[b];
            float best = 0.0f, entsum = 0.0f;
            #pragma unroll
            for (int m = 0; m < MDL; m++) {
                float tval = *(const float*)(slot + m * ROWB + 4 * tgt);
                float mean = ssum[m] * (1.0f / CDIM);
                float sc   = mean - tval;            // ce - ent - logC
                entsum += __logf(sexp[m]) - mean - LOGC;
                if (m == 0 || sc < best) {           // strict <: jax first-min
                    if (m == 0) { best = sc; }
                    else        { best = sc; win = m; }
                }
            }
            acc0 += (double)(best + LOGC);           // ce_win - ent_win
            acc1 += (double)entsum;
            if (idx_out) idx_out[b] = (float)win;
        }
        win = __shfl_sync(0xFFFFFFFFu, win, 0);

        // Oracle row copy straight from smem (vector loads, scalar stores:
        // dst may be only 4B-aligned).
        if (oracle) {
            const float4* __restrict__ src4 =
                (const float4*)(slot + win * ROWB);
            float* __restrict__ dst = oracle + (size_t)b * CDIM;
            #pragma unroll
            for (int k = 0; k < 8; k++) {
                int i = lane + 32 * k;
                if (i < NV4) {
                    float4 v = src4[i];
                    dst[4 * i + 0] = v.x;
                    dst[4 * i + 1] = v.y;
                    dst[4 * i + 2] = v.z;
                    dst[4 * i + 3] = v.w;
                }
            }
        }

        __syncwarp();                   // all lanes done reading slot s
        if (lane == 0 && n + DEPTH < cnt) fill(s, n + DEPTH);
    }

    // Stream tail: one atomic pair per warp; block counter finalizes.
    if (lane == 0 && cnt > 0) {
        atomicAdd(&g_acc[0], acc0);
        atomicAdd(&g_acc[1], acc1);
        __threadfence();
    }
    __syncthreads();
    if (tid == 0) {
        unsigned t = atomicAdd(&g_count, 1u);
        if (t == (unsigned)gridDim.x - 1u) {
            double a0 = __longlong_as_double(
                atomicExch((unsigned long long*)&g_acc[0], 0ull));
            double a1 = __longlong_as_double(
                atomicExch((unsigned long long*)&g_acc[1], 0ull));
            if (loss_out) loss_out[0] = (float)((a0 + a1) / (double)B);
            g_count = 0u;
            __threadfence();
        }
    }
}

extern "C" void kernel_launch(void* const* d_in, const int* in_sizes, int n_in,
                              void* d_out, int out_size)
{
    const float* logits = (const float*)d_in[0];
    const int*   t32    = (const int*)d_in[1];
    const int B = in_sizes[1];                 // 8192

    float* out = (float*)d_out;
    const long long bc = (long long)B * CDIM;

    // Output layout: tuple (new_loss, oracle_logits, min_index) flattened.
    float* loss_p   = nullptr;
    float* oracle_p = nullptr;
    float* idx_p    = nullptr;
    long long osz = (long long)out_size;
    if (osz >= 1 + bc + B) {                   // full tuple
        loss_p   = out;
        oracle_p = out + 1;
        idx_p    = out + 1 + bc;
    } else if (osz == bc + B) {                // (oracle, idx)
        oracle_p = out;
        idx_p    = out + bc;
    } else if (osz == bc) {                    // oracle only
        oracle_p = out;
    } else if (osz == B) {                     // idx only
        idx_p = out;
    } else {                                   // scalar loss only
        loss_p = out;
    }

    const int grid = (B + QB - 1) / QB;        // 147 blocks (~1 per SM)

    cudaFuncSetAttribute(cmcl_warp,
                         cudaFuncAttributeMaxDynamicSharedMemorySize, DYNSM);
    cmcl_warp<<<grid, NTHR, DYNSM>>>(logits, t32, loss_p, oracle_p, idx_p, B);
}